// round 7
// baseline (speedup 1.0000x reference)
#include <cuda_runtime.h>
#include <cstdint>

#define MAX_NODES 100000
#define MAX_EDGES 1600000
#define IN_C  32
#define HID_C 64
#define OUT_C 32
#define SCAN_CHUNK 1024
#define MAX_CHUNKS 128   // ceil(100000/1024)=98

// Scratch (__device__ globals: allocation-free rule)
__device__ __align__(16) float g_agg1[MAX_NODES * IN_C];    // 12.8 MB (raw sums)
__device__ __align__(16) float g_hw  [MAX_NODES * OUT_C];   // relu(h) @ W2_l
__device__ __align__(16) float g_hr  [MAX_NODES * OUT_C];   // relu(h) @ W2_r
__device__ int g_deg   [MAX_NODES];
__device__ int g_rowptr[MAX_NODES + 1];
__device__ int g_cursor[MAX_NODES];
__device__ int g_col   [MAX_EDGES];                         // 6.4 MB
__device__ int g_chunkSum[MAX_CHUNKS];
__device__ int g_chunkOff[MAX_CHUNKS + 1];

// ---------------------------------------------------------------------------
// Packed f32x2 helpers (Blackwell FFMA2)
// ---------------------------------------------------------------------------
__device__ __forceinline__ void fma2(unsigned long long& d,
                                     unsigned long long a,
                                     unsigned long long b)
{
    asm("fma.rn.f32x2 %0, %1, %2, %0;" : "+l"(d) : "l"(a), "l"(b));
}
__device__ __forceinline__ unsigned long long pack2(float v)
{
    unsigned long long r;
    asm("mov.b64 %0, {%1, %1};" : "=l"(r) : "r"(__float_as_uint(v)));
    return r;
}
__device__ __forceinline__ float2 unpack2(unsigned long long v)
{
    float2 f;
    asm("mov.b64 {%0, %1}, %2;" : "=f"(f.x), "=f"(f.y) : "l"(v));
    return f;
}

// ---------------------------------------------------------------------------
// CSR build step 1: degree histogram over destinations
// ---------------------------------------------------------------------------
__global__ void deg_count(const int* __restrict__ dst, int* __restrict__ deg,
                          int n_edges)
{
    int e = blockIdx.x * blockDim.x + threadIdx.x;
    if (e < n_edges) atomicAdd(&deg[dst[e]], 1);
}

// CSR step 2a: per-chunk exclusive scan (deterministic). 256 thr x 4 elems.
__global__ void scan1(const int* __restrict__ deg, int* __restrict__ pref,
                      int* __restrict__ chunkSum, int n)
{
    __shared__ int sT[256];
    int chunk = blockIdx.x;
    int base  = chunk * SCAN_CHUNK;
    int t     = threadIdx.x;

    int v[4], s = 0;
#pragma unroll
    for (int j = 0; j < 4; j++) {
        int idx = base + t * 4 + j;
        v[j] = (idx < n) ? deg[idx] : 0;
        s += v[j];
    }
    sT[t] = s;
    __syncthreads();
#pragma unroll
    for (int off = 1; off < 256; off <<= 1) {
        int y = (t >= off) ? sT[t - off] : 0;
        __syncthreads();
        sT[t] += y;
        __syncthreads();
    }
    int excl = sT[t] - s;   // exclusive prefix of this thread's 4-group
#pragma unroll
    for (int j = 0; j < 4; j++) {
        int idx = base + t * 4 + j;
        if (idx < n) pref[idx] = excl;
        excl += v[j];
    }
    if (t == 255) chunkSum[chunk] = sT[255];
}

// CSR step 2b: serial scan of chunk sums (98 elems — trivial)
__global__ void scan2(const int* __restrict__ chunkSum, int* __restrict__ chunkOff,
                      int nchunks)
{
    if (threadIdx.x == 0 && blockIdx.x == 0) {
        int s = 0;
        for (int i = 0; i < nchunks; i++) { chunkOff[i] = s; s += chunkSum[i]; }
        chunkOff[nchunks] = s;
    }
}

// CSR step 2c: add chunk offsets; init cursor; close row_ptr
__global__ void scan3(int* __restrict__ rowptr, int* __restrict__ cursor,
                      const int* __restrict__ chunkOff, int n, int nchunks)
{
    int i = blockIdx.x * blockDim.x + threadIdx.x;
    if (i < n) {
        int v = rowptr[i] + chunkOff[i / SCAN_CHUNK];
        rowptr[i] = v;
        cursor[i] = v;
    }
    if (i == 0) rowptr[n] = chunkOff[nchunks];
}

// CSR step 3: fill column (src) array
__global__ void csr_fill(const int* __restrict__ src, const int* __restrict__ dst,
                         int* __restrict__ cursor, int* __restrict__ col,
                         int n_edges)
{
    int e = blockIdx.x * blockDim.x + threadIdx.x;
    if (e >= n_edges) return;
    int d = dst[e];
    int pos = atomicAdd(&cursor[d], 1);
    col[pos] = src[e];
}

// ---------------------------------------------------------------------------
// CSR gather, C=32: one warp per node. 4 edges/iter x 8 float4 segments;
// cross-lane shfl reduction; no atomics.
//   FUSE_OUT=false: agg[n,:] = raw sum            (layer 1)
//   FUSE_OUT=true : out[n,:] = sum/max(deg,1) + b + hr[n,:]   (layer 2 + final)
// ---------------------------------------------------------------------------
template <bool FUSE_OUT>
__global__ __launch_bounds__(256)
void gather32(const float* __restrict__ feat,
              const int* __restrict__ rowptr,
              const int* __restrict__ col,
              const float* __restrict__ b,
              const float* __restrict__ hr,
              float* __restrict__ outp,
              int n_nodes)
{
    int warp = (blockIdx.x * blockDim.x + threadIdx.x) >> 5;
    int lane = threadIdx.x & 31;
    if (warp >= n_nodes) return;
    int node = warp;

    int beg = rowptr[node];
    int end = rowptr[node + 1];

    int sub = lane >> 3;   // which of 4 edges this iter
    int seg = lane & 7;    // float4 segment

    float4 acc = {0.f, 0.f, 0.f, 0.f};
    for (int i = beg; i < end; i += 4) {
        int cv = (lane < 4 && i + lane < end) ? __ldg(col + i + lane) : 0;
        int c  = __shfl_sync(0xffffffffu, cv, sub);
        if (i + sub < end) {
            float4 v = *(const float4*)(feat + (long long)c * 32 + seg * 4);
            acc.x += v.x; acc.y += v.y; acc.z += v.z; acc.w += v.w;
        }
    }
    // reduce across the 4 sub-lanes (lanes seg, seg+8, seg+16, seg+24)
#pragma unroll
    for (int off = 8; off < 32; off <<= 1) {
        acc.x += __shfl_xor_sync(0xffffffffu, acc.x, off);
        acc.y += __shfl_xor_sync(0xffffffffu, acc.y, off);
        acc.z += __shfl_xor_sync(0xffffffffu, acc.z, off);
        acc.w += __shfl_xor_sync(0xffffffffu, acc.w, off);
    }
    if (lane < 8) {
        if (FUSE_OUT) {
            float inv = 1.0f / fmaxf((float)(end - beg), 1.0f);
            float4 bb = __ldg((const float4*)(b + seg * 4));
            float4 rr = *(const float4*)(hr + (long long)node * 32 + seg * 4);
            float4 o;
            o.x = acc.x * inv + bb.x + rr.x;
            o.y = acc.y * inv + bb.y + rr.y;
            o.z = acc.z * inv + bb.z + rr.z;
            o.w = acc.w * inv + bb.w + rr.w;
            *(float4*)(outp + (long long)node * 32 + seg * 4) = o;
        } else {
            *(float4*)(outp + (long long)node * 32 + seg * 4) = acc;
        }
    }
}

// ---------------------------------------------------------------------------
// Fused layer-1 transform + both layer-2 projections (h stays in registers):
//   h  = relu( (agg1/max(deg,1)) @ W1l + b1 + x @ W1r )
//   hw = h @ W2l ,  hr = h @ W2r
// ---------------------------------------------------------------------------
__global__ __launch_bounds__(256)
void transform_l1_fused(const float* __restrict__ x,
                        const float* __restrict__ agg,
                        const int* __restrict__ rowptr,
                        const float* __restrict__ Wl,
                        const float* __restrict__ b,
                        const float* __restrict__ Wr,
                        const float* __restrict__ W2l,
                        const float* __restrict__ W2r,
                        float* __restrict__ hw,
                        float* __restrict__ hr,
                        int n_nodes)
{
    __shared__ __align__(16) float sWl [IN_C  * HID_C];
    __shared__ __align__(16) float sWr [IN_C  * HID_C];
    __shared__ __align__(16) float sW2l[HID_C * OUT_C];
    __shared__ __align__(16) float sW2r[HID_C * OUT_C];
    __shared__ float sB[HID_C];

    for (int i = threadIdx.x * 4; i < IN_C * HID_C; i += 256 * 4) {
        *(float4*)&sWl[i] = *(const float4*)&Wl[i];
        *(float4*)&sWr[i] = *(const float4*)&Wr[i];
    }
    for (int i = threadIdx.x * 4; i < HID_C * OUT_C; i += 256 * 4) {
        *(float4*)&sW2l[i] = *(const float4*)&W2l[i];
        *(float4*)&sW2r[i] = *(const float4*)&W2r[i];
    }
    if (threadIdx.x < HID_C) sB[threadIdx.x] = b[threadIdx.x];
    __syncthreads();

    int node = blockIdx.x * 256 + threadIdx.x;
    if (node >= n_nodes) return;

    int deg = rowptr[node + 1] - rowptr[node];
    float inv = 1.0f / fmaxf((float)deg, 1.0f);

    unsigned long long acc[HID_C / 2];
#pragma unroll
    for (int i = 0; i < HID_C / 2; i++) acc[i] = 0ull;

    // Pass 1: (agg/deg) @ W1l
    {
        const float4* arow = (const float4*)(agg + (long long)node * IN_C);
#pragma unroll
        for (int kc = 0; kc < IN_C / 4; kc++) {
            float4 a4 = arow[kc];
            float av[4] = {a4.x * inv, a4.y * inv, a4.z * inv, a4.w * inv};
#pragma unroll
            for (int j = 0; j < 4; j++) {
                unsigned long long av2 = pack2(av[j]);
                const int k = kc * 4 + j;
#pragma unroll
                for (int c = 0; c < HID_C; c += 4) {
                    ulonglong2 w2 = *(const ulonglong2*)&sWl[k * HID_C + c];
                    fma2(acc[c / 2],     av2, w2.x);
                    fma2(acc[c / 2 + 1], av2, w2.y);
                }
            }
        }
    }
    // Pass 2: x @ W1r
    {
        const float4* xrow = (const float4*)(x + (long long)node * IN_C);
#pragma unroll
        for (int kc = 0; kc < IN_C / 4; kc++) {
            float4 a4 = xrow[kc];
            float av[4] = {a4.x, a4.y, a4.z, a4.w};
#pragma unroll
            for (int j = 0; j < 4; j++) {
                unsigned long long av2 = pack2(av[j]);
                const int k = kc * 4 + j;
#pragma unroll
                for (int c = 0; c < HID_C; c += 4) {
                    ulonglong2 w2 = *(const ulonglong2*)&sWr[k * HID_C + c];
                    fma2(acc[c / 2],     av2, w2.x);
                    fma2(acc[c / 2 + 1], av2, w2.y);
                }
            }
        }
    }

    // Bias + ReLU -> h in registers only
    float hval[HID_C];
#pragma unroll
    for (int c = 0; c < HID_C; c += 2) {
        float2 p = unpack2(acc[c / 2]);
        hval[c + 0] = fmaxf(p.x + sB[c + 0], 0.0f);
        hval[c + 1] = fmaxf(p.y + sB[c + 1], 0.0f);
    }

    // Pass 3+4: hw = h @ W2l, hr = h @ W2r
    unsigned long long accL[OUT_C / 2], accR[OUT_C / 2];
#pragma unroll
    for (int i = 0; i < OUT_C / 2; i++) { accL[i] = 0ull; accR[i] = 0ull; }
#pragma unroll
    for (int k = 0; k < HID_C; k++) {
        unsigned long long av2 = pack2(hval[k]);
#pragma unroll
        for (int c = 0; c < OUT_C; c += 4) {
            ulonglong2 wl = *(const ulonglong2*)&sW2l[k * OUT_C + c];
            fma2(accL[c / 2],     av2, wl.x);
            fma2(accL[c / 2 + 1], av2, wl.y);
            ulonglong2 wr = *(const ulonglong2*)&sW2r[k * OUT_C + c];
            fma2(accR[c / 2],     av2, wr.x);
            fma2(accR[c / 2 + 1], av2, wr.y);
        }
    }
    float* hwrow = hw + (long long)node * OUT_C;
    float* hrrow = hr + (long long)node * OUT_C;
#pragma unroll
    for (int c = 0; c < OUT_C; c += 4) {
        float2 l0 = unpack2(accL[c / 2]);
        float2 l1 = unpack2(accL[c / 2 + 1]);
        float4 ol = {l0.x, l0.y, l1.x, l1.y};
        *(float4*)&hwrow[c] = ol;
        float2 r0 = unpack2(accR[c / 2]);
        float2 r1 = unpack2(accR[c / 2 + 1]);
        float4 orr = {r0.x, r0.y, r1.x, r1.y};
        *(float4*)&hrrow[c] = orr;
    }
}

// ---------------------------------------------------------------------------
// Launch
// ---------------------------------------------------------------------------
extern "C" void kernel_launch(void* const* d_in, const int* in_sizes, int n_in,
                              void* d_out, int out_size)
{
    const float* x    = (const float*)d_in[0];
    const int*   ei   = (const int*)d_in[1];     // [2, E] int32
    const float* W1l  = (const float*)d_in[2];
    const float* b1   = (const float*)d_in[3];
    const float* W1r  = (const float*)d_in[4];
    const float* W2l  = (const float*)d_in[5];
    const float* b2   = (const float*)d_in[6];
    const float* W2r  = (const float*)d_in[7];
    float*       out  = (float*)d_out;

    const int n_nodes = in_sizes[0] / IN_C;
    const int n_edges = in_sizes[1] / 2;
    const int nchunks = (n_nodes + SCAN_CHUNK - 1) / SCAN_CHUNK;

    const int* src = ei;
    const int* dst = ei + n_edges;

    float *agg1, *hw, *hr;
    int *deg, *rowptr, *cursor, *col, *chunkSum, *chunkOff;
    cudaGetSymbolAddress((void**)&agg1,     g_agg1);
    cudaGetSymbolAddress((void**)&hw,       g_hw);
    cudaGetSymbolAddress((void**)&hr,       g_hr);
    cudaGetSymbolAddress((void**)&deg,      g_deg);
    cudaGetSymbolAddress((void**)&rowptr,   g_rowptr);
    cudaGetSymbolAddress((void**)&cursor,   g_cursor);
    cudaGetSymbolAddress((void**)&col,      g_col);
    cudaGetSymbolAddress((void**)&chunkSum, g_chunkSum);
    cudaGetSymbolAddress((void**)&chunkOff, g_chunkOff);

    // --- CSR build (same graph reused by both layers) ---
    cudaMemsetAsync(deg, 0, (size_t)n_nodes * sizeof(int));
    deg_count<<<(n_edges + 255) / 256, 256>>>(dst, deg, n_edges);
    scan1<<<nchunks, 256>>>(deg, rowptr, chunkSum, n_nodes);
    scan2<<<1, 32>>>(chunkSum, chunkOff, nchunks);
    scan3<<<(n_nodes + 255) / 256, 256>>>(rowptr, cursor, chunkOff, n_nodes, nchunks);
    csr_fill<<<(n_edges + 255) / 256, 256>>>(src, dst, cursor, col, n_edges);

    const int gather_blocks = (n_nodes * 32 + 255) / 256;

    // Layer 1 aggregate: gather raw sums (transform divides by deg)
    gather32<false><<<gather_blocks, 256>>>(x, rowptr, col, nullptr, nullptr,
                                            agg1, n_nodes);

    // Fused: layer-1 transform + hw (=h@W2l) + hr (=h@W2r)
    transform_l1_fused<<<(n_nodes + 255) / 256, 256>>>(
        x, agg1, rowptr, W1l, b1, W1r, W2l, W2r, hw, hr, n_nodes);

    // Layer 2 aggregate fused with final combine:
    // out = gather(hw)/max(deg,1) + b2 + hr
    gather32<true><<<gather_blocks, 256>>>(hw, rowptr, col, b2, hr,
                                           out, n_nodes);
}